// round 15
// baseline (speedup 1.0000x reference)
#include <cuda_runtime.h>
#include <cstdint>

typedef unsigned int u32;
typedef unsigned long long u64;

#define BATCH 8
#define CH    64
#define HW    4096
#define CQn   8
#define CVn   32
#define NP    1024
#define NCH   64          // 16-key chunks
#define EPSBN 1e-5f
#define LOG2E 1.4426950408889634f

__device__ float g_Q [(size_t)BATCH*HW*CQn];      // [b][n][8]
__device__ uint4 g_Kf[(size_t)BATCH*NCH*32];      // K frags {kh0,kl0,kh1,kl1}
__device__ uint4 g_Vf[(size_t)BATCH*NCH*2*32];    // V frags {a0,a1,b0,b1}

// ---------------- helpers ----------------
__device__ __forceinline__ u64 pk2(float lo, float hi) {
    u64 r; asm("mov.b64 %0,{%1,%2};" : "=l"(r) : "f"(lo), "f"(hi)); return r;
}
__device__ __forceinline__ void upk2(u64 v, float& lo, float& hi) {
    asm("mov.b64 {%0,%1},%2;" : "=f"(lo), "=f"(hi) : "l"(v));
}
__device__ __forceinline__ u64 ffma2(u64 a, u64 b, u64 c) {
    u64 d; asm("fma.rn.f32x2 %0,%1,%2,%3;" : "=l"(d) : "l"(a), "l"(b), "l"(c)); return d;
}
__device__ __forceinline__ float ex2f(float x) {
    float y; asm("ex2.approx.f32 %0,%1;" : "=f"(y) : "f"(x)); return y;
}
__device__ __forceinline__ u32 pkh(float a, float b) {   // a->lo half, b->hi half
    u32 r; asm("cvt.rn.f16x2.f32 %0,%1,%2;" : "=r"(r) : "f"(b), "f"(a)); return r;
}
__device__ __forceinline__ u32 ex2h2(u32 a) {            // packed f16x2 exp2
    u32 r; asm("ex2.approx.f16x2 %0,%1;" : "=r"(r) : "r"(a)); return r;
}
__device__ __forceinline__ u32 hadd2(u32 a, u32 b) {
    u32 r; asm("add.f16x2 %0,%1,%2;" : "=r"(r) : "r"(a), "r"(b)); return r;
}
__device__ __forceinline__ float f16lo(u32 a) {
    float f; asm("{.reg .b16 x,y; mov.b32 {x,y},%1; cvt.f32.f16 %0,x;}" : "=f"(f) : "r"(a));
    return f;
}
__device__ __forceinline__ float f16hi(u32 a) {
    float f; asm("{.reg .b16 x,y; mov.b32 {x,y},%1; cvt.f32.f16 %0,y;}" : "=f"(f) : "r"(a));
    return f;
}
__device__ __forceinline__ void hsplit(float a, float b, u32& hi, u32& lo) {
    u32 h = pkh(a, b);
    float fa, fb;
    asm("{.reg .b16 x,y; mov.b32 {x,y},%2; cvt.f32.f16 %0,x; cvt.f32.f16 %1,y;}"
        : "=f"(fa), "=f"(fb) : "r"(h));
    hi = h; lo = pkh(a - fa, b - fb);
}
__device__ __forceinline__ void mma16816(float* d, const u32* a, u32 b0, u32 b1) {
    asm("mma.sync.aligned.m16n8k16.row.col.f32.f16.f16.f32 "
        "{%0,%1,%2,%3},{%4,%5,%6,%7},{%8,%9},{%0,%1,%2,%3};"
        : "+f"(d[0]), "+f"(d[1]), "+f"(d[2]), "+f"(d[3])
        : "r"(a[0]), "r"(a[1]), "r"(a[2]), "r"(a[3]), "r"(b0), "r"(b1));
}
__device__ __forceinline__ void mma1688(float* d, u32 a0, u32 a1, u32 b0) {
    asm("mma.sync.aligned.m16n8k8.row.col.f32.f16.f16.f32 "
        "{%0,%1,%2,%3},{%4,%5},{%6},{%0,%1,%2,%3};"
        : "+f"(d[0]), "+f"(d[1]), "+f"(d[2]), "+f"(d[3])
        : "r"(a0), "r"(a1), "r"(b0));
}

// ---------------- kernel 1: Q + pooled K/V + MMA fragment packing ----------
// Weight layouts in smem are CH-MAJOR: wqs[ch][8], wks[ch][8], wvs[ch][32].
__global__ __launch_bounds__(256) void prep_kernel(
    const float* __restrict__ mem,
    const float* __restrict__ wq, const float* __restrict__ bq,
    const float* __restrict__ qs, const float* __restrict__ qb,
    const float* __restrict__ qm, const float* __restrict__ qv,
    const float* __restrict__ wk, const float* __restrict__ bk,
    const float* __restrict__ ks, const float* __restrict__ kb,
    const float* __restrict__ km, const float* __restrict__ kv,
    const float* __restrict__ wv, const float* __restrict__ bv,
    const float* __restrict__ vs, const float* __restrict__ vb,
    const float* __restrict__ vm, const float* __restrict__ vv)
{
    __shared__ float tile[CH*128];
    __shared__ __align__(16) float wqs[CQn*CH];       // [ch][8]
    __shared__ __align__(16) float wks[CQn*CH];       // [ch][8]
    __shared__ __align__(16) float wvs[CVn*CH + 64];  // [ch][32]
    __shared__ float cqs[CQn], cks[CQn], cvs[CVn];
    float* kst = wqs;                 // reused after compute: [8][32]
    float* vst = wvs;                 // reused after compute: [32][33]

    int t  = threadIdx.x;
    int b  = blockIdx.x >> 5;
    int h2 = blockIdx.x & 31;

    for (int i = t; i < CQn*CH; i += 256) {
        int oc = i >> 6, ch = i & 63;
        float iq = qs[oc] * rsqrtf(qv[oc] + EPSBN);
        float ik = ks[oc] * rsqrtf(kv[oc] + EPSBN);
        wqs[ch*8 + oc] = wq[i] * iq;
        wks[ch*8 + oc] = wk[i] * ik * LOG2E;
    }
    for (int i = t; i < CVn*CH; i += 256) {
        int oc = i >> 6, ch = i & 63;
        float iv = vs[oc] * rsqrtf(vv[oc] + EPSBN);
        wvs[ch*32 + oc] = wv[i] * iv;
    }
    if (t < CQn) {
        float iq = qs[t] * rsqrtf(qv[t] + EPSBN);
        float ik = ks[t] * rsqrtf(kv[t] + EPSBN);
        cqs[t] = bq[t]*iq + qb[t] - qm[t]*iq;
        cks[t] = (bk[t]*ik + kb[t] - km[t]*ik) * LOG2E;
    }
    if (t < CVn) {
        float iv = vs[t] * rsqrtf(vv[t] + EPSBN);
        cvs[t] = bv[t]*iv + vb[t] - vm[t]*iv;
    }

    const float4* src = (const float4*)(mem + (size_t)b*CH*HW + (size_t)h2*128);
    float4* t4 = (float4*)tile;
    for (int i = t; i < CH*32; i += 256) {
        int c = i >> 5, j = i & 31;
        t4[i] = src[(size_t)c*(HW/4) + j];
    }
    __syncthreads();

    {   // Q: thread -> (4 ch, 1 px); weights via broadcast LDS.128, f32x2 FMA
        int p = t & 127, half = t >> 7;
        int oc0 = half * 4;
        u64 a01 = 0ULL, a23 = 0ULL;
        const u64* wq2 = (const u64*)&wqs[oc0];
        #pragma unroll 8
        for (int ch = 0; ch < CH; ch++) {
            float m = tile[ch*128 + p];
            u64 m2 = pk2(m, m);
            a01 = ffma2(wq2[ch*4    ], m2, a01);
            a23 = ffma2(wq2[ch*4 + 1], m2, a23);
        }
        float q0, q1, q2, q3;
        upk2(a01, q0, q1); upk2(a23, q2, q3);
        size_t n = (size_t)b*HW + h2*128 + p;
        float4 o = make_float4(q0 + cqs[oc0], q1 + cqs[oc0+1],
                               q2 + cqs[oc0+2], q3 + cqs[oc0+3]);
        *(float4*)&g_Q[n*CQn + oc0] = o;
    }

    float kval;                    // K pooled: broadcast weight + paired tile
    {
        int i = t & 31, oc = t >> 5;
        u64 aP = 0ULL, aQ = 0ULL;
        int p0 = 2*i, p2 = 64 + 2*i;
        #pragma unroll 4
        for (int ch = 0; ch < CH; ch++) {
            float w = wks[ch*8 + oc];
            u64 w2 = pk2(w, w);
            u64 m01 = *(const u64*)&tile[ch*128 + p0];
            u64 m23 = *(const u64*)&tile[ch*128 + p2];
            aP = ffma2(w2, m01, aP);
            aQ = ffma2(w2, m23, aQ);
        }
        float a0, a1, a2, a3;
        upk2(aP, a0, a1); upk2(aQ, a2, a3);
        kval = fmaxf(fmaxf(a0,a1), fmaxf(a2,a3)) + cks[oc];
    }

    float vo[4];                   // V pooled: LDS.128 weights + paired tile
    {
        int i = t & 31, gr = t >> 5;
        int oc0 = gr * 4;
        u64 acc[4][2];
        #pragma unroll
        for (int a = 0; a < 4; a++) { acc[a][0] = 0ULL; acc[a][1] = 0ULL; }
        int p0 = 2*i, p2 = 64 + 2*i;
        const u64* wv2 = (const u64*)&wvs[oc0];
        #pragma unroll 2
        for (int ch = 0; ch < CH; ch++) {
            u64 w01 = wv2[ch*16], w23 = wv2[ch*16 + 1];
            float w0, w1, w2, w3;
            upk2(w01, w0, w1); upk2(w23, w2, w3);
            u64 wd0 = pk2(w0, w0), wd1 = pk2(w1, w1);
            u64 wd2 = pk2(w2, w2), wd3 = pk2(w3, w3);
            u64 m01 = *(const u64*)&tile[ch*128 + p0];
            u64 m23 = *(const u64*)&tile[ch*128 + p2];
            acc[0][0] = ffma2(wd0, m01, acc[0][0]); acc[0][1] = ffma2(wd0, m23, acc[0][1]);
            acc[1][0] = ffma2(wd1, m01, acc[1][0]); acc[1][1] = ffma2(wd1, m23, acc[1][1]);
            acc[2][0] = ffma2(wd2, m01, acc[2][0]); acc[2][1] = ffma2(wd2, m23, acc[2][1]);
            acc[3][0] = ffma2(wd3, m01, acc[3][0]); acc[3][1] = ffma2(wd3, m23, acc[3][1]);
        }
        #pragma unroll
        for (int a = 0; a < 4; a++) {
            float x0, x1, x2, x3;
            upk2(acc[a][0], x0, x1); upk2(acc[a][1], x2, x3);
            vo[a] = fmaxf(fmaxf(x0,x1), fmaxf(x2,x3)) + cvs[oc0+a];
        }
    }

    __syncthreads();
    {
        int i = t & 31, oc = t >> 5;
        kst[oc*32 + i] = kval;
        int oc0 = (t >> 5) * 4;
        #pragma unroll
        for (int a = 0; a < 4; a++) vst[(oc0+a)*33 + i] = vo[a];
    }
    __syncthreads();

    if (t < 64) {                  // K fragments
        int cc = t >> 5, lane = t & 31, g = lane >> 2, tq = lane & 3;
        int k0 = cc*16 + g, k1 = k0 + 8;
        u32 h0,l0,h1,l1;
        hsplit(kst[(2*tq)*32 + k0], kst[(2*tq+1)*32 + k0], h0, l0);
        hsplit(kst[(2*tq)*32 + k1], kst[(2*tq+1)*32 + k1], h1, l1);
        g_Kf[((size_t)b*NCH + h2*2 + cc)*32 + lane] = make_uint4(h0, l0, h1, l1);
    }
    if (t < 128) {                 // V fragments
        int cc = t >> 6, jj = (t >> 5) & 1, lane = t & 31;
        int g = lane >> 2, tq = lane & 3;
        int k0 = cc*16 + 2*tq, chA = jj*16 + g, chB = chA + 8;
        u32 a0 = pkh(vst[chA*33 + k0],     vst[chA*33 + k0 + 1]);
        u32 a1 = pkh(vst[chA*33 + k0 + 8], vst[chA*33 + k0 + 9]);
        u32 b0 = pkh(vst[chB*33 + k0],     vst[chB*33 + k0 + 1]);
        u32 b1 = pkh(vst[chB*33 + k0 + 8], vst[chB*33 + k0 + 9]);
        g_Vf[(((size_t)b*NCH + h2*2 + cc)*2 + jj)*32 + lane] = make_uint4(a0, a1, b0, b1);
    }
}

// ---------------- kernel 2: flash attention, in-CTA split-K ----------------
// 512 thr = 16 warps: warps 0-7 do chunks 0-31, warps 8-15 do 32-63, same
// 8 query-tiles. grid (32, BATCH) = 256 CTAs, 2 CTAs/SM -> 32 warps/SM.
#define NT    512
#define SKF_N 2048
#define SVF_N 4096
#define SMEM_ATTN ((SKF_N + SVF_N)*16 + CH*CVn*4 + CH*4)
#define SG1_OFF (128*33)                 // half-1 staging offset (floats)
#define SSM_OFF (2*128*33)               // (s, mx) staging offset (floats)

__global__ __launch_bounds__(NT, 2) void attn_kernel(
    const float* __restrict__ x, float* __restrict__ out,
    const float* __restrict__ wp, const float* __restrict__ bp,
    const float* __restrict__ ps, const float* __restrict__ pb,
    const float* __restrict__ pm, const float* __restrict__ pv,
    const float* __restrict__ gamma)
{
    extern __shared__ char smem[];
    uint4* sKf = (uint4*)smem;
    uint4* sVf = sKf + SKF_N;
    float* sWp = (float*)(sVf + SVF_N);  // [ch][32]
    float* sCp = sWp + CH*CVn;
    float* sG  = (float*)smem;           // alias after loop (K + head of V)

    int t = threadIdx.x, lane = t & 31, wid = t >> 5;
    int half = wid >> 3, tile = wid & 7;
    int g = lane >> 2, tq = lane & 3;
    int b = blockIdx.y;
    float gam = gamma[0];

    {   // flat fragment copy-in (shared by both K-halves)
        const uint4* gk = &g_Kf[(size_t)b*NCH*32];
        for (int i = t; i < SKF_N; i += NT) sKf[i] = gk[i];
        const uint4* gv = &g_Vf[(size_t)b*NCH*2*32];
        for (int i = t; i < SVF_N; i += NT) sVf[i] = gv[i];
        for (int i = t; i < CH*CVn; i += NT) {
            int c = i >> 5;
            float ip = ps[c] * rsqrtf(pv[c] + EPSBN);
            sWp[i] = gam * ip * wp[i];
        }
        if (t < CH) {
            float ip = ps[t] * rsqrtf(pv[t] + EPSBN);
            sCp[t] = gam * (bp[t]*ip + pb[t] - pm[t]*ip);
        }
    }
    __syncthreads();

    // ---- Q fragments: tile = wid&7 -> 16 queries (shared by both halves)
    int qb = blockIdx.x*128 + tile*16;
    u32 A0[4];
    {
        const float* Qb = &g_Q[((size_t)b*HW + qb)*CQn + 2*tq];
        hsplit(Qb[(g    )*8], Qb[(g    )*8 + 1], A0[0], A0[2]);
        hsplit(Qb[(g + 8)*8], Qb[(g + 8)*8 + 1], A0[1], A0[3]);
    }

    float mxA = -1e30f, mxB = -1e30f;
    float s0 = 0.f, s1 = 0.f;
    float acc[4][4];
    #pragma unroll
    for (int j = 0; j < 4; j++)
        #pragma unroll
        for (int i = 0; i < 4; i++) acc[j][i] = 0.f;

    int cbeg = half*32, cend = cbeg + 32;
    #pragma unroll 1
    for (int c = cbeg; c < cend; c++) {
        uint4 kf = sKf[c*32 + lane];
        uint4 v0 = sVf[(c*2    )*32 + lane];
        uint4 v1 = sVf[(c*2 + 1)*32 + lane];

        float l0[4] = {0.f,0.f,0.f,0.f}, l1[4] = {0.f,0.f,0.f,0.f};
        mma16816(l0, A0, kf.x, kf.x); mma1688(l0, A0[0], A0[1], kf.y);
        mma16816(l1, A0, kf.z, kf.z); mma1688(l1, A0[0], A0[1], kf.w);

        float cA = fmaxf(fmaxf(l0[0], l0[1]), fmaxf(l1[0], l1[1]));
        float cB = fmaxf(fmaxf(l0[2], l0[3]), fmaxf(l1[2], l1[3]));
        if (__any_sync(0xffffffffu, (cA > mxA) || (cB > mxB))) {
            cA = fmaxf(cA, __shfl_xor_sync(0xffffffffu, cA, 1));
            cA = fmaxf(cA, __shfl_xor_sync(0xffffffffu, cA, 2));
            cB = fmaxf(cB, __shfl_xor_sync(0xffffffffu, cB, 1));
            cB = fmaxf(cB, __shfl_xor_sync(0xffffffffu, cB, 2));
            float nA = fmaxf(mxA, cA + 4.0f);
            float nB = fmaxf(mxB, cB + 4.0f);
            float fA = ex2f(mxA - nA), fB = ex2f(mxB - nB);
            mxA = nA; mxB = nB;
            s0 *= fA; s1 *= fB;
            #pragma unroll
            for (int j = 0; j < 4; j++) {
                acc[j][0] *= fA; acc[j][1] *= fA;
                acc[j][2] *= fB; acc[j][3] *= fB;
            }
        }

        u32 P[4];
        P[0] = ex2h2(pkh(l0[0]-mxA, l0[1]-mxA));
        P[1] = ex2h2(pkh(l0[2]-mxB, l0[3]-mxB));
        P[2] = ex2h2(pkh(l1[0]-mxA, l1[1]-mxA));
        P[3] = ex2h2(pkh(l1[2]-mxB, l1[3]-mxB));

        u32 hA = hadd2(P[0], P[2]);
        u32 hB = hadd2(P[1], P[3]);
        s0 += f16lo(hA) + f16hi(hA);
        s1 += f16lo(hB) + f16hi(hB);

        mma16816(acc[0], P, v0.x, v0.y);
        mma16816(acc[1], P, v0.z, v0.w);
        mma16816(acc[2], P, v1.x, v1.y);
        mma16816(acc[3], P, v1.z, v1.w);
    }

    // ---- quad-reduce denominators (full row sums for this half)
    s0 += __shfl_xor_sync(0xffffffffu, s0, 1);
    s0 += __shfl_xor_sync(0xffffffffu, s0, 2);
    s1 += __shfl_xor_sync(0xffffffffu, s1, 1);
    s1 += __shfl_xor_sync(0xffffffffu, s1, 2);

    __syncthreads();   // all fragment reads done -> safe to alias staging
    {
        int r0 = half*SG1_OFF + (tile*16 + g)*33;
        int r1 = r0 + 8*33;
        #pragma unroll
        for (int j = 0; j < 4; j++) {
            int cb = j*8 + 2*tq;
            sG[r0 + cb    ] = acc[j][0];
            sG[r0 + cb + 1] = acc[j][1];
            sG[r1 + cb    ] = acc[j][2];
            sG[r1 + cb + 1] = acc[j][3];
        }
        if (tq == 0) {
            float2* sSM = (float2*)(sG + SSM_OFF);
            sSM[half*128 + tile*16 + g    ] = make_float2(s0, mxA);
            sSM[half*128 + tile*16 + g + 8] = make_float2(s1, mxB);
        }
    }
    __syncthreads();

    // ---- merge halves + projection + residual; 4 threads/query (16 ch each)
    int q = t & 127, quarter = t >> 7;
    const float2* sSM = (const float2*)(sG + SSM_OFF);
    float2 pL = sSM[q], pH = sSM[128 + q];
    float m  = fmaxf(pL.y, pH.y);
    float fL = ex2f(pL.y - m), fH = ex2f(pH.y - m);
    float inv = 1.0f / (pL.x*fL + pH.x*fH);
    fL *= inv; fH *= inv;

    u64 gp[16];
    {
        const float* grL = &sG[q*33];
        const float* grH = &sG[SG1_OFF + q*33];
        #pragma unroll
        for (int i = 0; i < 16; i++)
            gp[i] = pk2(grL[2*i]*fL + grH[2*i]*fH,
                        grL[2*i+1]*fL + grH[2*i+1]*fH);
    }

    size_t base = (size_t)b*CH*HW + (size_t)blockIdx.x*128 + q;
    int c0 = quarter*16;
    #pragma unroll 4
    for (int cc = 0; cc < 16; cc++) {
        int c2 = c0 + cc;
        const u64* w2 = (const u64*)&sWp[c2*32];
        u64 d = 0ULL;
        #pragma unroll
        for (int i = 0; i < 16; i++) d = ffma2(gp[i], w2[i], d);
        float lo, hi; upk2(d, lo, hi);
        float val = lo + hi + sCp[c2];
        out[base + (size_t)c2*HW] = __ldg(&x[base + (size_t)c2*HW]) + val;
    }
}

// ---------------- launch ----------------
extern "C" void kernel_launch(void* const* d_in, const int* in_sizes, int n_in,
                              void* d_out, int out_size)
{
    (void)in_sizes; (void)n_in; (void)out_size;
    const float* x   = (const float*)d_in[0];
    const float* mem = (const float*)d_in[1];

    cudaFuncSetAttribute(attn_kernel,
                         cudaFuncAttributeMaxDynamicSharedMemorySize, SMEM_ATTN);

    prep_kernel<<<BATCH*32, 256>>>(mem,
        (const float*)d_in[2],  (const float*)d_in[3],  (const float*)d_in[4],
        (const float*)d_in[5],  (const float*)d_in[6],  (const float*)d_in[7],
        (const float*)d_in[8],  (const float*)d_in[9],  (const float*)d_in[10],
        (const float*)d_in[11], (const float*)d_in[12], (const float*)d_in[13],
        (const float*)d_in[14], (const float*)d_in[15], (const float*)d_in[16],
        (const float*)d_in[17], (const float*)d_in[18], (const float*)d_in[19]);

    attn_kernel<<<dim3(32, BATCH), NT, SMEM_ATTN>>>(x, (float*)d_out,
        (const float*)d_in[20], (const float*)d_in[21], (const float*)d_in[22],
        (const float*)d_in[23], (const float*)d_in[24], (const float*)d_in[25],
        (const float*)d_in[26]);
}

// round 16
// speedup vs baseline: 1.0897x; 1.0897x over previous
#include <cuda_runtime.h>
#include <cstdint>

typedef unsigned int u32;
typedef unsigned long long u64;

#define BATCH 8
#define CH    64
#define HW    4096
#define CQn   8
#define CVn   32
#define NP    1024
#define NCH   64          // 16-key chunks
#define EPSBN 1e-5f
#define LOG2E 1.4426950408889634f

__device__ float g_Q [(size_t)BATCH*HW*CQn];      // [b][n][8]
__device__ uint4 g_Kf[(size_t)BATCH*NCH*32];      // K frags {kh0,kl0,kh1,kl1}
__device__ uint4 g_Vf[(size_t)BATCH*NCH*2*32];    // V frags {a0,a1,b0,b1}

// ---------------- helpers ----------------
__device__ __forceinline__ u64 pk2(float lo, float hi) {
    u64 r; asm("mov.b64 %0,{%1,%2};" : "=l"(r) : "f"(lo), "f"(hi)); return r;
}
__device__ __forceinline__ void upk2(u64 v, float& lo, float& hi) {
    asm("mov.b64 {%0,%1},%2;" : "=f"(lo), "=f"(hi) : "l"(v));
}
__device__ __forceinline__ u64 ffma2(u64 a, u64 b, u64 c) {
    u64 d; asm("fma.rn.f32x2 %0,%1,%2,%3;" : "=l"(d) : "l"(a), "l"(b), "l"(c)); return d;
}
__device__ __forceinline__ float ex2f(float x) {
    float y; asm("ex2.approx.f32 %0,%1;" : "=f"(y) : "f"(x)); return y;
}
__device__ __forceinline__ u32 pkh(float a, float b) {   // a->lo half, b->hi half
    u32 r; asm("cvt.rn.f16x2.f32 %0,%1,%2;" : "=r"(r) : "f"(b), "f"(a)); return r;
}
__device__ __forceinline__ u32 ex2h2(u32 a) {            // packed f16x2 exp2
    u32 r; asm("ex2.approx.f16x2 %0,%1;" : "=r"(r) : "r"(a)); return r;
}
__device__ __forceinline__ u32 hadd2(u32 a, u32 b) {
    u32 r; asm("add.f16x2 %0,%1,%2;" : "=r"(r) : "r"(a), "r"(b)); return r;
}
__device__ __forceinline__ float f16lo(u32 a) {
    float f; asm("{.reg .b16 x,y; mov.b32 {x,y},%1; cvt.f32.f16 %0,x;}" : "=f"(f) : "r"(a));
    return f;
}
__device__ __forceinline__ float f16hi(u32 a) {
    float f; asm("{.reg .b16 x,y; mov.b32 {x,y},%1; cvt.f32.f16 %0,y;}" : "=f"(f) : "r"(a));
    return f;
}
__device__ __forceinline__ void hsplit(float a, float b, u32& hi, u32& lo) {
    u32 h = pkh(a, b);
    float fa, fb;
    asm("{.reg .b16 x,y; mov.b32 {x,y},%2; cvt.f32.f16 %0,x; cvt.f32.f16 %1,y;}"
        : "=f"(fa), "=f"(fb) : "r"(h));
    hi = h; lo = pkh(a - fa, b - fb);
}
__device__ __forceinline__ void mma16816(float* d, const u32* a, u32 b0, u32 b1) {
    asm("mma.sync.aligned.m16n8k16.row.col.f32.f16.f16.f32 "
        "{%0,%1,%2,%3},{%4,%5,%6,%7},{%8,%9},{%0,%1,%2,%3};"
        : "+f"(d[0]), "+f"(d[1]), "+f"(d[2]), "+f"(d[3])
        : "r"(a[0]), "r"(a[1]), "r"(a[2]), "r"(a[3]), "r"(b0), "r"(b1));
}
__device__ __forceinline__ void mma1688(float* d, u32 a0, u32 a1, u32 b0) {
    asm("mma.sync.aligned.m16n8k8.row.col.f32.f16.f16.f32 "
        "{%0,%1,%2,%3},{%4,%5},{%6},{%0,%1,%2,%3};"
        : "+f"(d[0]), "+f"(d[1]), "+f"(d[2]), "+f"(d[3])
        : "r"(a0), "r"(a1), "r"(b0));
}

// ---------------- kernel 1: split prep --------------------------------------
// grid (BATCH*32, 2): part 0 -> Q + pooled K + K fragments;
//                     part 1 -> pooled V + V fragments.
// Inner loops identical to the proven R14 versions.
__global__ __launch_bounds__(256) void prep_kernel(
    const float* __restrict__ mem,
    const float* __restrict__ wq, const float* __restrict__ bq,
    const float* __restrict__ qs, const float* __restrict__ qb,
    const float* __restrict__ qm, const float* __restrict__ qv,
    const float* __restrict__ wk, const float* __restrict__ bk,
    const float* __restrict__ ks, const float* __restrict__ kb,
    const float* __restrict__ km, const float* __restrict__ kv,
    const float* __restrict__ wv, const float* __restrict__ bv,
    const float* __restrict__ vs, const float* __restrict__ vb,
    const float* __restrict__ vm, const float* __restrict__ vv)
{
    __shared__ float tile[CH*128];
    __shared__ float wqs[CQn*CH], wks[CQn*CH], wvs[CVn*CH + 64];
    __shared__ float cqs[CQn], cks[CQn], cvs[CVn];
    float* kst = wqs;                 // reused after compute: [8][32]
    float* vst = wvs;                 // reused after compute: [32][33]

    int t  = threadIdx.x;
    int b  = blockIdx.x >> 5;
    int h2 = blockIdx.x & 31;
    int part = blockIdx.y;

    if (part == 0) {
        for (int i = t; i < CQn*CH; i += 256) {
            int c = i >> 6;
            float iq = qs[c] * rsqrtf(qv[c] + EPSBN);
            float ik = ks[c] * rsqrtf(kv[c] + EPSBN);
            wqs[i] = wq[i] * iq;
            wks[i] = wk[i] * ik * LOG2E;
        }
        if (t < CQn) {
            float iq = qs[t] * rsqrtf(qv[t] + EPSBN);
            float ik = ks[t] * rsqrtf(kv[t] + EPSBN);
            cqs[t] = bq[t]*iq + qb[t] - qm[t]*iq;
            cks[t] = (bk[t]*ik + kb[t] - km[t]*ik) * LOG2E;
        }
    } else {
        for (int i = t; i < CVn*CH; i += 256) {
            int c = i >> 6;
            float iv = vs[c] * rsqrtf(vv[c] + EPSBN);
            wvs[i] = wv[i] * iv;
        }
        if (t < CVn) {
            float iv = vs[t] * rsqrtf(vv[t] + EPSBN);
            cvs[t] = bv[t]*iv + vb[t] - vm[t]*iv;
        }
    }

    const float4* src = (const float4*)(mem + (size_t)b*CH*HW + (size_t)h2*128);
    float4* t4 = (float4*)tile;
    for (int i = t; i < CH*32; i += 256) {
        int c = i >> 5, j = i & 31;
        t4[i] = src[(size_t)c*(HW/4) + j];
    }
    __syncthreads();

    if (part == 0) {
        {   // Q: 8 ch x 128 px ; thread -> (4 ch, 1 px)
            int p = t & 127, half = t >> 7;
            int oc0 = half * 4;
            float a0 = 0.f, a1 = 0.f, a2 = 0.f, a3 = 0.f;
            const float* w0 = &wqs[oc0*CH];
            #pragma unroll 8
            for (int ch = 0; ch < CH; ch++) {
                float m = tile[ch*128 + p];
                a0 += w0[ch]*m; a1 += w0[CH+ch]*m;
                a2 += w0[2*CH+ch]*m; a3 += w0[3*CH+ch]*m;
            }
            size_t n = (size_t)b*HW + h2*128 + p;
            float4 o = make_float4(a0 + cqs[oc0], a1 + cqs[oc0+1],
                                   a2 + cqs[oc0+2], a3 + cqs[oc0+3]);
            *(float4*)&g_Q[n*CQn + oc0] = o;
        }

        float kval;                // K pooled
        {
            int i = t & 31, oc = t >> 5;
            float a0 = 0.f, a1 = 0.f, a2 = 0.f, a3 = 0.f;
            const float* w = &wks[oc*CH];
            int p0 = 2*i, p2 = 64 + 2*i;
            #pragma unroll 4
            for (int ch = 0; ch < CH; ch++) {
                float wv_ = w[ch];
                const float* tr = &tile[ch*128];
                a0 += wv_*tr[p0]; a1 += wv_*tr[p0+1];
                a2 += wv_*tr[p2]; a3 += wv_*tr[p2+1];
            }
            kval = fmaxf(fmaxf(a0,a1), fmaxf(a2,a3)) + cks[oc];
        }

        __syncthreads();
        {
            int i = t & 31, oc = t >> 5;
            kst[oc*32 + i] = kval;
        }
        __syncthreads();

        if (t < 64) {              // K fragments
            int cc = t >> 5, lane = t & 31, g = lane >> 2, tq = lane & 3;
            int k0 = cc*16 + g, k1 = k0 + 8;
            u32 h0,l0,h1,l1;
            hsplit(kst[(2*tq)*32 + k0], kst[(2*tq+1)*32 + k0], h0, l0);
            hsplit(kst[(2*tq)*32 + k1], kst[(2*tq+1)*32 + k1], h1, l1);
            g_Kf[((size_t)b*NCH + h2*2 + cc)*32 + lane] = make_uint4(h0, l0, h1, l1);
        }
    } else {
        float vo[4];               // V pooled
        {
            int i = t & 31, gr = t >> 5;
            int oc0 = gr * 4;
            float acc[4][4];
            #pragma unroll
            for (int a = 0; a < 4; a++)
                #pragma unroll
                for (int c = 0; c < 4; c++) acc[a][c] = 0.f;
            int p0 = 2*i, p2 = 64 + 2*i;
            #pragma unroll 2
            for (int ch = 0; ch < CH; ch++) {
                const float* tr = &tile[ch*128];
                float m0 = tr[p0], m1 = tr[p0+1], m2 = tr[p2], m3 = tr[p2+1];
                #pragma unroll
                for (int a = 0; a < 4; a++) {
                    float wv_ = wvs[(oc0+a)*CH + ch];
                    acc[a][0] += wv_*m0; acc[a][1] += wv_*m1;
                    acc[a][2] += wv_*m2; acc[a][3] += wv_*m3;
                }
            }
            #pragma unroll
            for (int a = 0; a < 4; a++)
                vo[a] = fmaxf(fmaxf(acc[a][0],acc[a][1]),
                              fmaxf(acc[a][2],acc[a][3])) + cvs[oc0+a];
        }

        __syncthreads();
        {
            int i = t & 31;
            int oc0 = (t >> 5) * 4;
            #pragma unroll
            for (int a = 0; a < 4; a++) vst[(oc0+a)*33 + i] = vo[a];
        }
        __syncthreads();

        if (t < 128) {             // V fragments
            int cc = t >> 6, jj = (t >> 5) & 1, lane = t & 31;
            int g = lane >> 2, tq = lane & 3;
            int k0 = cc*16 + 2*tq, chA = jj*16 + g, chB = chA + 8;
            u32 a0 = pkh(vst[chA*33 + k0],     vst[chA*33 + k0 + 1]);
            u32 a1 = pkh(vst[chA*33 + k0 + 8], vst[chA*33 + k0 + 9]);
            u32 b0 = pkh(vst[chB*33 + k0],     vst[chB*33 + k0 + 1]);
            u32 b1 = pkh(vst[chB*33 + k0 + 8], vst[chB*33 + k0 + 9]);
            g_Vf[(((size_t)b*NCH + h2*2 + cc)*2 + jj)*32 + lane] = make_uint4(a0, a1, b0, b1);
        }
    }
}

// ---------------- kernel 2: flash attention, in-CTA split-K ----------------
// 512 thr = 16 warps: warps 0-7 do chunks 0-31, warps 8-15 do 32-63, same
// 8 query-tiles. grid (32, BATCH) = 256 CTAs, 2 CTAs/SM -> 32 warps/SM.
#define NT    512
#define SKF_N 2048
#define SVF_N 4096
#define SMEM_ATTN ((SKF_N + SVF_N)*16 + CH*CVn*4 + CH*4)
#define SG1_OFF (128*33)                 // half-1 staging offset (floats)
#define SSM_OFF (2*128*33)               // (s, mx) staging offset (floats)

__global__ __launch_bounds__(NT, 2) void attn_kernel(
    const float* __restrict__ x, float* __restrict__ out,
    const float* __restrict__ wp, const float* __restrict__ bp,
    const float* __restrict__ ps, const float* __restrict__ pb,
    const float* __restrict__ pm, const float* __restrict__ pv,
    const float* __restrict__ gamma)
{
    extern __shared__ char smem[];
    uint4* sKf = (uint4*)smem;
    uint4* sVf = sKf + SKF_N;
    float* sWp = (float*)(sVf + SVF_N);  // [ch][32]
    float* sCp = sWp + CH*CVn;
    float* sG  = (float*)smem;           // alias after loop (K + head of V)

    int t = threadIdx.x, lane = t & 31, wid = t >> 5;
    int half = wid >> 3, tile = wid & 7;
    int g = lane >> 2, tq = lane & 3;
    int b = blockIdx.y;
    float gam = gamma[0];

    {   // flat fragment copy-in (shared by both K-halves)
        const uint4* gk = &g_Kf[(size_t)b*NCH*32];
        for (int i = t; i < SKF_N; i += NT) sKf[i] = gk[i];
        const uint4* gv = &g_Vf[(size_t)b*NCH*2*32];
        for (int i = t; i < SVF_N; i += NT) sVf[i] = gv[i];
        for (int i = t; i < CH*CVn; i += NT) {
            int c = i >> 5;
            float ip = ps[c] * rsqrtf(pv[c] + EPSBN);
            sWp[i] = gam * ip * wp[i];
        }
        if (t < CH) {
            float ip = ps[t] * rsqrtf(pv[t] + EPSBN);
            sCp[t] = gam * (bp[t]*ip + pb[t] - pm[t]*ip);
        }
    }
    __syncthreads();

    // ---- Q fragments: tile = wid&7 -> 16 queries (shared by both halves)
    int qb = blockIdx.x*128 + tile*16;
    u32 A0[4];
    {
        const float* Qb = &g_Q[((size_t)b*HW + qb)*CQn + 2*tq];
        hsplit(Qb[(g    )*8], Qb[(g    )*8 + 1], A0[0], A0[2]);
        hsplit(Qb[(g + 8)*8], Qb[(g + 8)*8 + 1], A0[1], A0[3]);
    }

    float mxA = -1e30f, mxB = -1e30f;
    float s0 = 0.f, s1 = 0.f;
    float acc[4][4];
    #pragma unroll
    for (int j = 0; j < 4; j++)
        #pragma unroll
        for (int i = 0; i < 4; i++) acc[j][i] = 0.f;

    int cbeg = half*32, cend = cbeg + 32;
    #pragma unroll 1
    for (int c = cbeg; c < cend; c++) {
        uint4 kf = sKf[c*32 + lane];
        uint4 v0 = sVf[(c*2    )*32 + lane];
        uint4 v1 = sVf[(c*2 + 1)*32 + lane];

        float l0[4] = {0.f,0.f,0.f,0.f}, l1[4] = {0.f,0.f,0.f,0.f};
        mma16816(l0, A0, kf.x, kf.x); mma1688(l0, A0[0], A0[1], kf.y);
        mma16816(l1, A0, kf.z, kf.z); mma1688(l1, A0[0], A0[1], kf.w);

        float cA = fmaxf(fmaxf(l0[0], l0[1]), fmaxf(l1[0], l1[1]));
        float cB = fmaxf(fmaxf(l0[2], l0[3]), fmaxf(l1[2], l1[3]));
        if (__any_sync(0xffffffffu, (cA > mxA) || (cB > mxB))) {
            cA = fmaxf(cA, __shfl_xor_sync(0xffffffffu, cA, 1));
            cA = fmaxf(cA, __shfl_xor_sync(0xffffffffu, cA, 2));
            cB = fmaxf(cB, __shfl_xor_sync(0xffffffffu, cB, 1));
            cB = fmaxf(cB, __shfl_xor_sync(0xffffffffu, cB, 2));
            float nA = fmaxf(mxA, cA + 4.0f);
            float nB = fmaxf(mxB, cB + 4.0f);
            float fA = ex2f(mxA - nA), fB = ex2f(mxB - nB);
            mxA = nA; mxB = nB;
            s0 *= fA; s1 *= fB;
            #pragma unroll
            for (int j = 0; j < 4; j++) {
                acc[j][0] *= fA; acc[j][1] *= fA;
                acc[j][2] *= fB; acc[j][3] *= fB;
            }
        }

        u32 P[4];
        P[0] = ex2h2(pkh(l0[0]-mxA, l0[1]-mxA));
        P[1] = ex2h2(pkh(l0[2]-mxB, l0[3]-mxB));
        P[2] = ex2h2(pkh(l1[0]-mxA, l1[1]-mxA));
        P[3] = ex2h2(pkh(l1[2]-mxB, l1[3]-mxB));

        u32 hA = hadd2(P[0], P[2]);
        u32 hB = hadd2(P[1], P[3]);
        s0 += f16lo(hA) + f16hi(hA);
        s1 += f16lo(hB) + f16hi(hB);

        mma16816(acc[0], P, v0.x, v0.y);
        mma16816(acc[1], P, v0.z, v0.w);
        mma16816(acc[2], P, v1.x, v1.y);
        mma16816(acc[3], P, v1.z, v1.w);
    }

    // ---- quad-reduce denominators (full row sums for this half)
    s0 += __shfl_xor_sync(0xffffffffu, s0, 1);
    s0 += __shfl_xor_sync(0xffffffffu, s0, 2);
    s1 += __shfl_xor_sync(0xffffffffu, s1, 1);
    s1 += __shfl_xor_sync(0xffffffffu, s1, 2);

    __syncthreads();   // all fragment reads done -> safe to alias staging
    {
        int r0 = half*SG1_OFF + (tile*16 + g)*33;
        int r1 = r0 + 8*33;
        #pragma unroll
        for (int j = 0; j < 4; j++) {
            int cb = j*8 + 2*tq;
            sG[r0 + cb    ] = acc[j][0];
            sG[r0 + cb + 1] = acc[j][1];
            sG[r1 + cb    ] = acc[j][2];
            sG[r1 + cb + 1] = acc[j][3];
        }
        if (tq == 0) {
            float2* sSM = (float2*)(sG + SSM_OFF);
            sSM[half*128 + tile*16 + g    ] = make_float2(s0, mxA);
            sSM[half*128 + tile*16 + g + 8] = make_float2(s1, mxB);
        }
    }
    __syncthreads();

    // ---- merge halves + projection + residual; 4 threads/query (16 ch each)
    int q = t & 127, quarter = t >> 7;
    const float2* sSM = (const float2*)(sG + SSM_OFF);
    float2 pL = sSM[q], pH = sSM[128 + q];
    float m  = fmaxf(pL.y, pH.y);
    float fL = ex2f(pL.y - m), fH = ex2f(pH.y - m);
    float inv = 1.0f / (pL.x*fL + pH.x*fH);
    fL *= inv; fH *= inv;

    u64 gp[16];
    {
        const float* grL = &sG[q*33];
        const float* grH = &sG[SG1_OFF + q*33];
        #pragma unroll
        for (int i = 0; i < 16; i++)
            gp[i] = pk2(grL[2*i]*fL + grH[2*i]*fH,
                        grL[2*i+1]*fL + grH[2*i+1]*fH);
    }

    size_t base = (size_t)b*CH*HW + (size_t)blockIdx.x*128 + q;
    int c0 = quarter*16;
    #pragma unroll 4
    for (int cc = 0; cc < 16; cc++) {
        int c2 = c0 + cc;
        const u64* w2 = (const u64*)&sWp[c2*32];
        u64 d = 0ULL;
        #pragma unroll
        for (int i = 0; i < 16; i++) d = ffma2(gp[i], w2[i], d);
        float lo, hi; upk2(d, lo, hi);
        float val = lo + hi + sCp[c2];
        out[base + (size_t)c2*HW] = __ldg(&x[base + (size_t)c2*HW]) + val;
    }
}

// ---------------- launch ----------------
extern "C" void kernel_launch(void* const* d_in, const int* in_sizes, int n_in,
                              void* d_out, int out_size)
{
    (void)in_sizes; (void)n_in; (void)out_size;
    const float* x   = (const float*)d_in[0];
    const float* mem = (const float*)d_in[1];

    cudaFuncSetAttribute(attn_kernel,
                         cudaFuncAttributeMaxDynamicSharedMemorySize, SMEM_ATTN);

    prep_kernel<<<dim3(BATCH*32, 2), 256>>>(mem,
        (const float*)d_in[2],  (const float*)d_in[3],  (const float*)d_in[4],
        (const float*)d_in[5],  (const float*)d_in[6],  (const float*)d_in[7],
        (const float*)d_in[8],  (const float*)d_in[9],  (const float*)d_in[10],
        (const float*)d_in[11], (const float*)d_in[12], (const float*)d_in[13],
        (const float*)d_in[14], (const float*)d_in[15], (const float*)d_in[16],
        (const float*)d_in[17], (const float*)d_in[18], (const float*)d_in[19]);

    attn_kernel<<<dim3(32, BATCH), NT, SMEM_ATTN>>>(x, (float*)d_out,
        (const float*)d_in[20], (const float*)d_in[21], (const float*)d_in[22],
        (const float*)d_in[23], (const float*)d_in[24], (const float*)d_in[25],
        (const float*)d_in[26]);
}